// round 13
// baseline (speedup 1.0000x reference)
#include <cuda_runtime.h>
#include <cuda_fp16.h>
#include <math.h>
#include <cstdint>

// Problem constants
#define TOK    4096
#define DMODEL 1024
#define NEXP   8
#define HDIM   4096
#define NASSIGN (TOK*2)

#define BM 128
#define BN 128
#define BK 64              // k-halves per stage
#define NSTAGE 3
#define A_BYTES 16384      // 128 rows x 64 halves (128B/row)
#define B_BYTES 16384      // 64 rows x 128 halves (256B/row)
#define STAGE_BYTES (A_BYTES + B_BYTES)     // 32768
#define SMEM_TOTAL (NSTAGE*STAGE_BYTES)     // 98304 -> 2 CTAs/SM

#define CV_CHUNK 2048      // float4 per conversion ticket

// Scratch (device globals; allocation-free rule)
__device__ int    g_expert_off[NEXP+1];
__device__ int    g_perm_tok[NASSIGN];
__device__ int    g_inv_pos[NASSIGN];
__device__ int    g_tok_exp[NASSIGN];
__device__ float  g_tok_gate[NASSIGN];
__device__ int    g_cvTicket;               // reset by partition_kernel
__device__ __half g_xh[(size_t)TOK * DMODEL];
__device__ __half g_wfch[(size_t)NEXP * DMODEL * HDIM];
__device__ __half g_wprojh[(size_t)NEXP * HDIM * DMODEL];
__device__ __half g_hbufh[(size_t)NASSIGN * HDIM];
__device__ float  g_ybuf[(size_t)NASSIGN * DMODEL];

// ---------------------------------------------------------------------------
__device__ __forceinline__ uint32_t smem_u32(const void* p) {
    uint32_t a;
    asm("{ .reg .u64 t; cvta.to.shared.u64 t, %1; cvt.u32.u64 %0, t; }" : "=r"(a) : "l"(p));
    return a;
}
#define CP_ASYNC16(dst, src) \
    asm volatile("cp.async.cg.shared.global [%0], [%1], 16;" :: "r"(dst), "l"(src))
#define CP_COMMIT() asm volatile("cp.async.commit_group;")
#define CP_WAIT1()  asm volatile("cp.async.wait_group 1;")

#define LDSM_X4(R0,R1,R2,R3,ADDR) \
    asm volatile("ldmatrix.sync.aligned.m8n8.x4.shared.b16 {%0,%1,%2,%3}, [%4];" \
        : "=r"(R0),"=r"(R1),"=r"(R2),"=r"(R3) : "r"(ADDR))
#define LDSM_X4_T(R0,R1,R2,R3,ADDR) \
    asm volatile("ldmatrix.sync.aligned.m8n8.x4.trans.shared.b16 {%0,%1,%2,%3}, [%4];" \
        : "=r"(R0),"=r"(R1),"=r"(R2),"=r"(R3) : "r"(ADDR))

__device__ __forceinline__ void mma_fp16(float* c, const uint32_t* a, const uint32_t* b) {
    asm volatile(
        "mma.sync.aligned.m16n8k16.row.col.f32.f16.f16.f32 "
        "{%0,%1,%2,%3}, {%4,%5,%6,%7}, {%8,%9}, {%0,%1,%2,%3};"
        : "+f"(c[0]), "+f"(c[1]), "+f"(c[2]), "+f"(c[3])
        : "r"(a[0]), "r"(a[1]), "r"(a[2]), "r"(a[3]), "r"(b[0]), "r"(b[1]));
}

__device__ __forceinline__ float tanh_fast(float x) {
    float r; asm("tanh.approx.f32 %0, %1;" : "=f"(r) : "f"(x)); return r;
}
__device__ __forceinline__ float gelu_tanh(float v) {
    const float c = 0.7978845608028654f;
    float u = c * (v + 0.044715f * v * v * v);
    return 0.5f * v * (1.0f + tanh_fast(u));
}

// ---------------------------------------------------------------------------
// Merged router + w_fc conversion (R10 structure; w_proj moved to GEMM1).
// Grid 4736 x 256. Blocks with blockIdx%9==0, rblk<512 run the router for 8
// tokens first; all blocks grid-stride convert w_fc.
// ---------------------------------------------------------------------------
__global__ void __launch_bounds__(256) router_conv_kernel(
    const float* __restrict__ x, const float* __restrict__ noise,
    const float* __restrict__ wr, const float* __restrict__ br,
    const float* __restrict__ wn, const float* __restrict__ bn,
    float* __restrict__ gate1, __half* __restrict__ xh,
    const float* __restrict__ wfcs, __half* __restrict__ wfcd, int n4a)
{
    int lane = threadIdx.x & 31;
    int wid  = threadIdx.x >> 5;
    int tid  = threadIdx.x;

    int rblk = (blockIdx.x % 9 == 0) ? (int)(blockIdx.x / 9) : -1;
    if (rblk >= 0 && rblk < TOK/8) {
        int warp = rblk * 8 + wid;   // token id

        const float4* xr4 = reinterpret_cast<const float4*>(x + (size_t)warp * DMODEL);
        float4 xv4[8];
        #pragma unroll
        for (int j = 0; j < 8; j++) xv4[j] = xr4[j*32 + lane];

        __half2* xh2 = reinterpret_cast<__half2*>(xh + (size_t)warp * DMODEL);
        #pragma unroll
        for (int j = 0; j < 8; j++) {
            xh2[(j*32 + lane)*2 + 0] = __floats2half2_rn(xv4[j].x, xv4[j].y);
            xh2[(j*32 + lane)*2 + 1] = __floats2half2_rn(xv4[j].z, xv4[j].w);
        }

        float ar[8] = {0,0,0,0,0,0,0,0};
        float an[8] = {0,0,0,0,0,0,0,0};
        #pragma unroll
        for (int j = 0; j < 8; j++) {
            #pragma unroll
            for (int c = 0; c < 4; c++) {
                float xv = (c == 0) ? xv4[j].x : (c == 1) ? xv4[j].y : (c == 2) ? xv4[j].z : xv4[j].w;
                int d = j*128 + lane*4 + c;
                const float4* w4r = reinterpret_cast<const float4*>(wr + (size_t)d*8);
                const float4* w4n = reinterpret_cast<const float4*>(wn + (size_t)d*8);
                float4 r0 = w4r[0], r1 = w4r[1];
                float4 n0 = w4n[0], n1 = w4n[1];
                ar[0] = fmaf(xv, r0.x, ar[0]); ar[1] = fmaf(xv, r0.y, ar[1]);
                ar[2] = fmaf(xv, r0.z, ar[2]); ar[3] = fmaf(xv, r0.w, ar[3]);
                ar[4] = fmaf(xv, r1.x, ar[4]); ar[5] = fmaf(xv, r1.y, ar[5]);
                ar[6] = fmaf(xv, r1.z, ar[6]); ar[7] = fmaf(xv, r1.w, ar[7]);
                an[0] = fmaf(xv, n0.x, an[0]); an[1] = fmaf(xv, n0.y, an[1]);
                an[2] = fmaf(xv, n0.z, an[2]); an[3] = fmaf(xv, n0.w, an[3]);
                an[4] = fmaf(xv, n1.x, an[4]); an[5] = fmaf(xv, n1.y, an[5]);
                an[6] = fmaf(xv, n1.z, an[6]); an[7] = fmaf(xv, n1.w, an[7]);
            }
        }
        #pragma unroll
        for (int e = 0; e < 8; e++) {
            #pragma unroll
            for (int o = 16; o > 0; o >>= 1) {
                ar[e] += __shfl_xor_sync(0xffffffffu, ar[e], o);
                an[e] += __shfl_xor_sync(0xffffffffu, an[e], o);
            }
        }
        if (lane == 0) {
            float nv[8];
            float mx = -1e30f;
            #pragma unroll
            for (int e = 0; e < 8; e++) {
                float l  = ar[e] + br[e];
                float nl = an[e] + bn[e];
                float sp = fmaxf(nl, 0.0f) + log1pf(expf(-fabsf(nl)));
                float v = l + noise[(size_t)warp*8 + e] * sp;
                nv[e] = v;
                mx = fmaxf(mx, v);
            }
            float s = 0.0f;
            #pragma unroll
            for (int e = 0; e < 8; e++) s += expf(nv[e] - mx);
            float inv = 1.0f / s;
            #pragma unroll
            for (int e = 0; e < 8; e++) gate1[(size_t)warp*8 + e] = expf(nv[e] - mx) * inv;
            int i0 = 0;
            #pragma unroll
            for (int e = 1; e < 8; e++) if (nv[e] > nv[i0]) i0 = e;
            int i1 = -1;
            #pragma unroll
            for (int e = 0; e < 8; e++) {
                if (e == i0) continue;
                if (i1 < 0 || nv[e] > nv[i1]) i1 = e;
            }
            float ex = expf(nv[i1] - nv[i0]);
            float den = 1.0f + ex;
            g_tok_exp[warp*2 + 0]  = i0;
            g_tok_exp[warp*2 + 1]  = i1;
            g_tok_gate[warp*2 + 0] = 1.0f / den;
            g_tok_gate[warp*2 + 1] = ex / den;
        }
    }

    // grid-stride w_fc conversion (all blocks)
    int i = blockIdx.x * blockDim.x + tid;
    int stride = gridDim.x * blockDim.x;
    for (; i < n4a; i += stride) {
        float4 v = reinterpret_cast<const float4*>(wfcs)[i];
        __half2 h0 = __floats2half2_rn(v.x, v.y);
        __half2 h1 = __floats2half2_rn(v.z, v.w);
        reinterpret_cast<__half2*>(wfcd)[2*i]   = h0;
        reinterpret_cast<__half2*>(wfcd)[2*i+1] = h1;
    }
}

// ---------------------------------------------------------------------------
// Deterministic stable partition, parallel scans. 1024 threads, 8 assigns each.
// Also resets the conversion ticket counter for the following GEMM1 launch.
// ---------------------------------------------------------------------------
__global__ void __launch_bounds__(1024) partition_kernel()
{
    __shared__ int wtot[32][8];
    __shared__ int wbase[32][8];
    __shared__ int ebase[9];
    int tid = threadIdx.x, lane = tid & 31, w = tid >> 5;
    int a0 = tid * 8;

    if (tid == 0) g_cvTicket = 0;

    int ex[8];
    int local[8] = {0,0,0,0,0,0,0,0};
    #pragma unroll
    for (int i = 0; i < 8; i++) { ex[i] = g_tok_exp[a0 + i]; local[ex[i]]++; }

    int incl[8];
    #pragma unroll
    for (int e = 0; e < 8; e++) incl[e] = local[e];
    #pragma unroll
    for (int off = 1; off < 32; off <<= 1) {
        #pragma unroll
        for (int e = 0; e < 8; e++) {
            int v = __shfl_up_sync(0xffffffffu, incl[e], off);
            if (lane >= off) incl[e] += v;
        }
    }
    if (lane == 31) {
        #pragma unroll
        for (int e = 0; e < 8; e++) wtot[w][e] = incl[e];
    }
    __syncthreads();

    if (w == 0) {
        int t[8], ti[8];
        #pragma unroll
        for (int e = 0; e < 8; e++) { t[e] = wtot[lane][e]; ti[e] = t[e]; }
        #pragma unroll
        for (int off = 1; off < 32; off <<= 1) {
            #pragma unroll
            for (int e = 0; e < 8; e++) {
                int v = __shfl_up_sync(0xffffffffu, ti[e], off);
                if (lane >= off) ti[e] += v;
            }
        }
        #pragma unroll
        for (int e = 0; e < 8; e++) wbase[lane][e] = ti[e] - t[e];
        if (lane == 31) {
            int acc = 0;
            #pragma unroll
            for (int e = 0; e < 8; e++) { ebase[e] = acc; acc += ti[e]; }
            ebase[8] = acc;
            #pragma unroll
            for (int e = 0; e <= 8; e++) g_expert_off[e] = ebase[e];
        }
    }
    __syncthreads();

    int pos[8];
    #pragma unroll
    for (int e = 0; e < 8; e++) pos[e] = ebase[e] + wbase[w][e] + incl[e] - local[e];
    #pragma unroll
    for (int i = 0; i < 8; i++) {
        int e = ex[i];
        int p = pos[e]++;
        g_perm_tok[p] = (a0 + i) >> 1;
        g_inv_pos[a0 + i] = p;
    }
}

// ---------------------------------------------------------------------------
// fp16 mma.sync GEMM — hot path byte-identical to R10 (125 regs, no slack).
// 128x128 tile, BK=64, 3-stage cp.async, 2 CTAs/SM; warp tile 32x64.
// IS_FC: EMPTY blocks (early exit) convert w_proj chunks via atomic tickets,
// fully contained in the early-exit branch (no values live across mainloop).
// ---------------------------------------------------------------------------
template<int K, int NTOT, bool IS_FC>
__global__ void __launch_bounds__(256, 2) moe_gemm_fp16(
    const __half* __restrict__ A,
    const __half* __restrict__ W,
    const float* __restrict__ bias,
    const float* __restrict__ cvs, __half* __restrict__ cvd, int cvn4)
{
    constexpr int NCH = K / BK;
    constexpr int NFRAG = 8;

    extern __shared__ char smem[];
    int e = blockIdx.y >> 6, m = blockIdx.y & 63;
    int off = g_expert_off[e];
    int cnt = g_expert_off[e+1] - off;
    if (m * BM >= cnt) {
        if (IS_FC) {
            __shared__ int s_t;
            int tid0 = threadIdx.x;
            for (;;) {
                if (tid0 == 0) s_t = atomicAdd(&g_cvTicket, 1);
                __syncthreads();
                int t = s_t;
                __syncthreads();
                int base = t * CV_CHUNK;
                if (base >= cvn4) break;
                #pragma unroll
                for (int j = 0; j < CV_CHUNK/256; j++) {
                    int i = base + j*256 + tid0;
                    if (i < cvn4) {
                        float4 v = reinterpret_cast<const float4*>(cvs)[i];
                        __half2 h0 = __floats2half2_rn(v.x, v.y);
                        __half2 h1 = __floats2half2_rn(v.z, v.w);
                        reinterpret_cast<__half2*>(cvd)[2*i]   = h0;
                        reinterpret_cast<__half2*>(cvd)[2*i+1] = h1;
                    }
                }
            }
        }
        return;
    }
    int mbase = off + m * BM;
    int rv = min(cnt - m * BM, BM);
    int n0 = blockIdx.x * BN;

    int tid = threadIdx.x;
    int lane = tid & 31, wid = tid >> 5;
    int wm = wid & 3, wn = wid >> 2;        // 4 x 2 warp grid
    int g = lane >> 2, tig = lane & 3;

    uint32_t sbase = smem_u32(smem);
    const __half* wbase = W + (size_t)e * K * NTOT + n0;

    // ---- staging descriptors ----
    const char* aSrc[4];
    #pragma unroll
    for (int i = 0; i < 4; i++) {
        int r = i*32 + (tid >> 3);
        int rr = min(r, rv - 1);
        int arow = IS_FC ? g_perm_tok[mbase + rr] : (mbase + rr);
        aSrc[i] = (const char*)(A + (size_t)arow * K) + (tid & 7) * 16;
    }
    uint32_t aDst0 = (uint32_t)((tid >> 3) * 128 + (((tid & 7) ^ ((tid >> 3) & 7)) * 16));
    const char* bSrc0 = (const char*)(wbase + (size_t)(tid >> 4) * NTOT) + (tid & 15) * 16;
    uint32_t bDst0 = (uint32_t)((tid >> 4) * 256 + ((((tid & 15)) ^ ((tid >> 4) & 7)) * 16));

    float acc[2][NFRAG][4];
    #pragma unroll
    for (int i = 0; i < 2; i++)
        #pragma unroll
        for (int j = 0; j < NFRAG; j++)
            #pragma unroll
            for (int v = 0; v < 4; v++) acc[i][j][v] = 0.0f;

    auto issue = [&](int kt, uint32_t stageOff) {
        uint32_t base = sbase + stageOff;
        #pragma unroll
        for (int i = 0; i < 4; i++)
            CP_ASYNC16(base + aDst0 + i * 4096, aSrc[i] + (size_t)kt * (BK*2));
        #pragma unroll
        for (int i = 0; i < 4; i++)
            CP_ASYNC16(base + A_BYTES + bDst0 + i * 4096,
                       bSrc0 + (size_t)kt * ((size_t)BK * NTOT * 2) + (size_t)i * (16*(size_t)NTOT*2));
    };

    issue(0, 0); CP_COMMIT();
    issue(1, STAGE_BYTES); CP_COMMIT();

    // per-lane ldmatrix offsets (kt/ks-invariant parts precomputed)
    int l15 = lane & 15;
    int lc  = lane >> 4;
    int sA7 = l15 & 7;
    uint32_t aOff[2];
    #pragma unroll
    for (int mf = 0; mf < 2; mf++)
        aOff[mf] = (uint32_t)((wm*32 + mf*16 + l15) * 128);
    uint32_t bOff[4];
    #pragma unroll
    for (int nf2 = 0; nf2 < 4; nf2++) {
        int nc = wn*8 + nf2*2 + lc;
        bOff[nf2] = (uint32_t)(l15*256 + ((nc ^ sA7) * 16));
    }

    uint32_t ldOff = 0, stOff = 2*STAGE_BYTES;

    for (int kt = 0; kt < NCH; kt++) {
        CP_WAIT1();
        __syncthreads();
        if (kt + 2 < NCH) issue(kt + 2, stOff);
        CP_COMMIT();

        uint32_t aBase = sbase + ldOff;
        uint32_t bBase = aBase + A_BYTES;

        #pragma unroll
        for (int ks = 0; ks < 4; ks++) {
            uint32_t kShiftA = (uint32_t)((((ks*2 + lc) ^ sA7) * 16));
            uint32_t af[2][4];
            #pragma unroll
            for (int mf = 0; mf < 2; mf++)
                LDSM_X4(af[mf][0], af[mf][1], af[mf][2], af[mf][3],
                        aBase + aOff[mf] + kShiftA);
            uint32_t bf[NFRAG][2];
            #pragma unroll
            for (int nf2 = 0; nf2 < NFRAG/2; nf2++)
                LDSM_X4_T(bf[2*nf2][0], bf[2*nf2][1], bf[2*nf2+1][0], bf[2*nf2+1][1],
                          bBase + (uint32_t)(ks*4096) + bOff[nf2]);
            #pragma unroll
            for (int mf = 0; mf < 2; mf++)
                #pragma unroll
                for (int nf = 0; nf < NFRAG; nf++)
                    mma_fp16(acc[mf][nf], af[mf], bf[nf]);
        }

        ldOff += STAGE_BYTES; if (ldOff == (uint32_t)SMEM_TOTAL) ldOff = 0;
        stOff += STAGE_BYTES; if (stOff == (uint32_t)SMEM_TOTAL) stOff = 0;
    }

    // ---- epilogue ----
    const float* brow = bias + (size_t)e * NTOT + n0;

    #pragma unroll
    for (int mf = 0; mf < 2; mf++) {
        int r0 = wm*32 + mf*16 + g;
        int r1 = r0 + 8;
        #pragma unroll
        for (int nf = 0; nf < NFRAG; nf++) {
            int col = wn*64 + nf*8 + tig*2;
            float2 bb = *reinterpret_cast<const float2*>(brow + col);
            if (IS_FC) {
                __half2* o0 = reinterpret_cast<__half2*>(g_hbufh + (size_t)(mbase + r0) * NTOT + n0 + col);
                __half2* o1 = reinterpret_cast<__half2*>(g_hbufh + (size_t)(mbase + r1) * NTOT + n0 + col);
                if (r0 < rv)
                    *o0 = __floats2half2_rn(gelu_tanh(acc[mf][nf][0] + bb.x),
                                            gelu_tanh(acc[mf][nf][1] + bb.y));
                if (r1 < rv)
                    *o1 = __floats2half2_rn(gelu_tanh(acc[mf][nf][2] + bb.x),
                                            gelu_tanh(acc[mf][nf][3] + bb.y));
            } else {
                float* o0 = g_ybuf + (size_t)(mbase + r0) * NTOT + n0 + col;
                float* o1 = g_ybuf + (size_t)(mbase + r1) * NTOT + n0 + col;
                if (r0 < rv) {
                    float2 o; o.x = acc[mf][nf][0] + bb.x; o.y = acc[mf][nf][1] + bb.y;
                    *reinterpret_cast<float2*>(o0) = o;
                }
                if (r1 < rv) {
                    float2 o; o.x = acc[mf][nf][2] + bb.x; o.y = acc[mf][nf][3] + bb.y;
                    *reinterpret_cast<float2*>(o1) = o;
                }
            }
        }
    }
}

// ---------------------------------------------------------------------------
// Combine: out[t] = g0 * y[p0] + g1 * y[p1]
// ---------------------------------------------------------------------------
__global__ void __launch_bounds__(256) combine_kernel(float* __restrict__ out)
{
    int t = blockIdx.x;
    int j = threadIdx.x;
    int p0 = g_inv_pos[2*t], p1 = g_inv_pos[2*t+1];
    float g0 = g_tok_gate[2*t], g1 = g_tok_gate[2*t+1];
    const float4* y0 = reinterpret_cast<const float4*>(g_ybuf + (size_t)p0 * DMODEL);
    const float4* y1 = reinterpret_cast<const float4*>(g_ybuf + (size_t)p1 * DMODEL);
    float4 a = y0[j], b = y1[j];
    float4 o;
    o.x = g0*a.x + g1*b.x; o.y = g0*a.y + g1*b.y;
    o.z = g0*a.z + g1*b.z; o.w = g0*a.w + g1*b.w;
    reinterpret_cast<float4*>(out + (size_t)t * DMODEL)[j] = o;
}

// ---------------------------------------------------------------------------
extern "C" void kernel_launch(void* const* d_in, const int* in_sizes, int n_in,
                              void* d_out, int out_size)
{
    const float* x      = (const float*)d_in[0];
    const float* noise  = (const float*)d_in[1];
    const float* wroute = (const float*)d_in[2];
    const float* broute = (const float*)d_in[3];
    const float* wnoise = (const float*)d_in[4];
    const float* bnoise = (const float*)d_in[5];
    const float* wfc    = (const float*)d_in[6];
    const float* bfc    = (const float*)d_in[7];
    const float* wproj  = (const float*)d_in[8];
    const float* bproj  = (const float*)d_in[9];

    float* out   = (float*)d_out;
    float* gate1 = out + (size_t)TOK * DMODEL;

    cudaFuncSetAttribute((const void*)moe_gemm_fp16<DMODEL, HDIM, true>,
        cudaFuncAttributeMaxDynamicSharedMemorySize, SMEM_TOTAL);
    cudaFuncSetAttribute((const void*)moe_gemm_fp16<HDIM, DMODEL, false>,
        cudaFuncAttributeMaxDynamicSharedMemorySize, SMEM_TOTAL);

    __half *xh_p, *wfch_p, *wprojh_p, *hbufh_p;
    cudaGetSymbolAddress((void**)&xh_p, g_xh);
    cudaGetSymbolAddress((void**)&wfch_p, g_wfch);
    cudaGetSymbolAddress((void**)&wprojh_p, g_wprojh);
    cudaGetSymbolAddress((void**)&hbufh_p, g_hbufh);

    // router + w_fc conversion
    router_conv_kernel<<<4736, 256>>>(
        x, noise, wroute, broute, wnoise, bnoise, gate1, xh_p,
        wfc, wfch_p, NEXP*DMODEL*HDIM/4);

    // partition (also resets the w_proj conversion ticket)
    partition_kernel<<<1, 1024>>>();

    // GEMM1; its empty CTAs convert w_proj (overlapped)
    dim3 g1(HDIM / BN, NEXP * 64);    // 32 x 512
    moe_gemm_fp16<DMODEL, HDIM, true><<<g1, 256, SMEM_TOTAL>>>(
        xh_p, wfch_p, bfc, wproj, wprojh_p, NEXP*HDIM*DMODEL/4);

    dim3 g2(DMODEL / BN, NEXP * 64);  // 8 x 512
    moe_gemm_fp16<HDIM, DMODEL, false><<<g2, 256, SMEM_TOTAL>>>(
        hbufh_p, wprojh_p, bproj, nullptr, nullptr, 0);

    combine_kernel<<<TOK, 256>>>(out);
}

// round 14
// speedup vs baseline: 1.0593x; 1.0593x over previous
#include <cuda_runtime.h>
#include <cuda_fp16.h>
#include <math.h>
#include <cstdint>

// Problem constants
#define TOK    4096
#define DMODEL 1024
#define NEXP   8
#define HDIM   4096
#define NASSIGN (TOK*2)

#define BM 128
#define BN 128
#define BK 64              // k-halves per stage
#define NSTAGE 3
#define A_BYTES 16384      // 128 rows x 64 halves (128B/row)
#define B_BYTES 16384      // 64 rows x 128 halves (256B/row)
#define STAGE_BYTES (A_BYTES + B_BYTES)     // 32768
#define SMEM_TOTAL (NSTAGE*STAGE_BYTES)     // 98304 -> 2 CTAs/SM
#define GPERS 296          // persistent CTAs (2 per SM x 148)

// Scratch (device globals; allocation-free rule)
__device__ int    g_expert_off[NEXP+1];
__device__ int    g_perm_tok[NASSIGN];
__device__ int    g_inv_pos[NASSIGN];
__device__ int    g_tok_exp[NASSIGN];
__device__ float  g_tok_gate[NASSIGN];
__device__ __half g_xh[(size_t)TOK * DMODEL];
__device__ __half g_wfch[(size_t)NEXP * DMODEL * HDIM];
__device__ __half g_wprojh[(size_t)NEXP * HDIM * DMODEL];
__device__ __half g_hbufh[(size_t)NASSIGN * HDIM];
__device__ float  g_ybuf[(size_t)NASSIGN * DMODEL];

// ---------------------------------------------------------------------------
__device__ __forceinline__ uint32_t smem_u32(const void* p) {
    uint32_t a;
    asm("{ .reg .u64 t; cvta.to.shared.u64 t, %1; cvt.u32.u64 %0, t; }" : "=r"(a) : "l"(p));
    return a;
}
#define CP_ASYNC16(dst, src) \
    asm volatile("cp.async.cg.shared.global [%0], [%1], 16;" :: "r"(dst), "l"(src))
#define CP_COMMIT() asm volatile("cp.async.commit_group;")
#define CP_WAIT1()  asm volatile("cp.async.wait_group 1;")

#define LDSM_X4(R0,R1,R2,R3,ADDR) \
    asm volatile("ldmatrix.sync.aligned.m8n8.x4.shared.b16 {%0,%1,%2,%3}, [%4];" \
        : "=r"(R0),"=r"(R1),"=r"(R2),"=r"(R3) : "r"(ADDR))
#define LDSM_X4_T(R0,R1,R2,R3,ADDR) \
    asm volatile("ldmatrix.sync.aligned.m8n8.x4.trans.shared.b16 {%0,%1,%2,%3}, [%4];" \
        : "=r"(R0),"=r"(R1),"=r"(R2),"=r"(R3) : "r"(ADDR))

__device__ __forceinline__ void mma_fp16(float* c, const uint32_t* a, const uint32_t* b) {
    asm volatile(
        "mma.sync.aligned.m16n8k16.row.col.f32.f16.f16.f32 "
        "{%0,%1,%2,%3}, {%4,%5,%6,%7}, {%8,%9}, {%0,%1,%2,%3};"
        : "+f"(c[0]), "+f"(c[1]), "+f"(c[2]), "+f"(c[3])
        : "r"(a[0]), "r"(a[1]), "r"(a[2]), "r"(a[3]), "r"(b[0]), "r"(b[1]));
}

__device__ __forceinline__ float tanh_fast(float x) {
    float r; asm("tanh.approx.f32 %0, %1;" : "=f"(r) : "f"(x)); return r;
}
__device__ __forceinline__ float gelu_tanh(float v) {
    const float c = 0.7978845608028654f;
    float u = c * (v + 0.044715f * v * v * v);
    return 0.5f * v * (1.0f + tanh_fast(u));
}

// ---------------------------------------------------------------------------
// Merged router + weight conversion (R10 structure, both tensors).
// ---------------------------------------------------------------------------
__global__ void __launch_bounds__(256) router_conv_kernel(
    const float* __restrict__ x, const float* __restrict__ noise,
    const float* __restrict__ wr, const float* __restrict__ br,
    const float* __restrict__ wn, const float* __restrict__ bn,
    float* __restrict__ gate1, __half* __restrict__ xh,
    const float* __restrict__ wfcs, __half* __restrict__ wfcd, int n4a,
    const float* __restrict__ wprojs, __half* __restrict__ wprojd, int n4b)
{
    int lane = threadIdx.x & 31;
    int wid  = threadIdx.x >> 5;
    int tid  = threadIdx.x;

    int rblk = (blockIdx.x % 9 == 0) ? (int)(blockIdx.x / 9) : -1;
    if (rblk >= 0 && rblk < TOK/8) {
        int warp = rblk * 8 + wid;   // token id

        const float4* xr4 = reinterpret_cast<const float4*>(x + (size_t)warp * DMODEL);
        float4 xv4[8];
        #pragma unroll
        for (int j = 0; j < 8; j++) xv4[j] = xr4[j*32 + lane];

        __half2* xh2 = reinterpret_cast<__half2*>(xh + (size_t)warp * DMODEL);
        #pragma unroll
        for (int j = 0; j < 8; j++) {
            xh2[(j*32 + lane)*2 + 0] = __floats2half2_rn(xv4[j].x, xv4[j].y);
            xh2[(j*32 + lane)*2 + 1] = __floats2half2_rn(xv4[j].z, xv4[j].w);
        }

        float ar[8] = {0,0,0,0,0,0,0,0};
        float an[8] = {0,0,0,0,0,0,0,0};
        #pragma unroll
        for (int j = 0; j < 8; j++) {
            #pragma unroll
            for (int c = 0; c < 4; c++) {
                float xv = (c == 0) ? xv4[j].x : (c == 1) ? xv4[j].y : (c == 2) ? xv4[j].z : xv4[j].w;
                int d = j*128 + lane*4 + c;
                const float4* w4r = reinterpret_cast<const float4*>(wr + (size_t)d*8);
                const float4* w4n = reinterpret_cast<const float4*>(wn + (size_t)d*8);
                float4 r0 = w4r[0], r1 = w4r[1];
                float4 n0 = w4n[0], n1 = w4n[1];
                ar[0] = fmaf(xv, r0.x, ar[0]); ar[1] = fmaf(xv, r0.y, ar[1]);
                ar[2] = fmaf(xv, r0.z, ar[2]); ar[3] = fmaf(xv, r0.w, ar[3]);
                ar[4] = fmaf(xv, r1.x, ar[4]); ar[5] = fmaf(xv, r1.y, ar[5]);
                ar[6] = fmaf(xv, r1.z, ar[6]); ar[7] = fmaf(xv, r1.w, ar[7]);
                an[0] = fmaf(xv, n0.x, an[0]); an[1] = fmaf(xv, n0.y, an[1]);
                an[2] = fmaf(xv, n0.z, an[2]); an[3] = fmaf(xv, n0.w, an[3]);
                an[4] = fmaf(xv, n1.x, an[4]); an[5] = fmaf(xv, n1.y, an[5]);
                an[6] = fmaf(xv, n1.z, an[6]); an[7] = fmaf(xv, n1.w, an[7]);
            }
        }
        #pragma unroll
        for (int e = 0; e < 8; e++) {
            #pragma unroll
            for (int o = 16; o > 0; o >>= 1) {
                ar[e] += __shfl_xor_sync(0xffffffffu, ar[e], o);
                an[e] += __shfl_xor_sync(0xffffffffu, an[e], o);
            }
        }
        if (lane == 0) {
            float nv[8];
            float mx = -1e30f;
            #pragma unroll
            for (int e = 0; e < 8; e++) {
                float l  = ar[e] + br[e];
                float nl = an[e] + bn[e];
                float sp = fmaxf(nl, 0.0f) + log1pf(expf(-fabsf(nl)));
                float v = l + noise[(size_t)warp*8 + e] * sp;
                nv[e] = v;
                mx = fmaxf(mx, v);
            }
            float s = 0.0f;
            #pragma unroll
            for (int e = 0; e < 8; e++) s += expf(nv[e] - mx);
            float inv = 1.0f / s;
            #pragma unroll
            for (int e = 0; e < 8; e++) gate1[(size_t)warp*8 + e] = expf(nv[e] - mx) * inv;
            int i0 = 0;
            #pragma unroll
            for (int e = 1; e < 8; e++) if (nv[e] > nv[i0]) i0 = e;
            int i1 = -1;
            #pragma unroll
            for (int e = 0; e < 8; e++) {
                if (e == i0) continue;
                if (i1 < 0 || nv[e] > nv[i1]) i1 = e;
            }
            float ex = expf(nv[i1] - nv[i0]);
            float den = 1.0f + ex;
            g_tok_exp[warp*2 + 0]  = i0;
            g_tok_exp[warp*2 + 1]  = i1;
            g_tok_gate[warp*2 + 0] = 1.0f / den;
            g_tok_gate[warp*2 + 1] = ex / den;
        }
    }

    // grid-stride weight conversion (all blocks, both tensors)
    int i = blockIdx.x * blockDim.x + tid;
    int stride = gridDim.x * blockDim.x;
    int total = n4a + n4b;
    for (; i < total; i += stride) {
        const float* s; __half* d; int j;
        if (i < n4a) { s = wfcs;   d = wfcd;   j = i; }
        else         { s = wprojs; d = wprojd; j = i - n4a; }
        float4 v = reinterpret_cast<const float4*>(s)[j];
        __half2 h0 = __floats2half2_rn(v.x, v.y);
        __half2 h1 = __floats2half2_rn(v.z, v.w);
        reinterpret_cast<__half2*>(d)[2*j]   = h0;
        reinterpret_cast<__half2*>(d)[2*j+1] = h1;
    }
}

// ---------------------------------------------------------------------------
// Deterministic stable partition, parallel scans. 1024 threads, 8 assigns each.
// ---------------------------------------------------------------------------
__global__ void __launch_bounds__(1024) partition_kernel()
{
    __shared__ int wtot[32][8];
    __shared__ int wbase[32][8];
    __shared__ int ebase[9];
    int tid = threadIdx.x, lane = tid & 31, w = tid >> 5;
    int a0 = tid * 8;

    int ex[8];
    int local[8] = {0,0,0,0,0,0,0,0};
    #pragma unroll
    for (int i = 0; i < 8; i++) { ex[i] = g_tok_exp[a0 + i]; local[ex[i]]++; }

    int incl[8];
    #pragma unroll
    for (int e = 0; e < 8; e++) incl[e] = local[e];
    #pragma unroll
    for (int off = 1; off < 32; off <<= 1) {
        #pragma unroll
        for (int e = 0; e < 8; e++) {
            int v = __shfl_up_sync(0xffffffffu, incl[e], off);
            if (lane >= off) incl[e] += v;
        }
    }
    if (lane == 31) {
        #pragma unroll
        for (int e = 0; e < 8; e++) wtot[w][e] = incl[e];
    }
    __syncthreads();

    if (w == 0) {
        int t[8], ti[8];
        #pragma unroll
        for (int e = 0; e < 8; e++) { t[e] = wtot[lane][e]; ti[e] = t[e]; }
        #pragma unroll
        for (int off = 1; off < 32; off <<= 1) {
            #pragma unroll
            for (int e = 0; e < 8; e++) {
                int v = __shfl_up_sync(0xffffffffu, ti[e], off);
                if (lane >= off) ti[e] += v;
            }
        }
        #pragma unroll
        for (int e = 0; e < 8; e++) wbase[lane][e] = ti[e] - t[e];
        if (lane == 31) {
            int acc = 0;
            #pragma unroll
            for (int e = 0; e < 8; e++) { ebase[e] = acc; acc += ti[e]; }
            ebase[8] = acc;
            #pragma unroll
            for (int e = 0; e <= 8; e++) g_expert_off[e] = ebase[e];
        }
    }
    __syncthreads();

    int pos[8];
    #pragma unroll
    for (int e = 0; e < 8; e++) pos[e] = ebase[e] + wbase[w][e] + incl[e] - local[e];
    #pragma unroll
    for (int i = 0; i < 8; i++) {
        int e = ex[i];
        int p = pos[e]++;
        g_perm_tok[p] = (a0 + i) >> 1;
        g_inv_pos[a0 + i] = p;
    }
}

// ---------------------------------------------------------------------------
// Persistent fp16 mma.sync GEMM. Grid = GPERS CTAs; each loops over the
// virtual tile grid (NX n-tiles x 512 m-slots) with static stride.
// Hot path identical to R10; one extra __syncthreads per tile guards smem.
// ---------------------------------------------------------------------------
template<int K, int NTOT, int NX, bool IS_FC>
__global__ void __launch_bounds__(256, 2) moe_gemm_fp16(
    const __half* __restrict__ A,
    const __half* __restrict__ W,
    const float* __restrict__ bias)
{
    constexpr int NCH = K / BK;
    constexpr int NFRAG = 8;
    constexpr int NTILES = NX * 512;

    extern __shared__ char smem[];
    int tid = threadIdx.x;
    int lane = tid & 31, wid = tid >> 5;
    int wm = wid & 3, wn = wid >> 2;        // 4 x 2 warp grid
    int g = lane >> 2, tig = lane & 3;
    uint32_t sbase = smem_u32(smem);

    // tile-invariant staging/ldmatrix constants
    uint32_t aDst0 = (uint32_t)((tid >> 3) * 128 + (((tid & 7) ^ ((tid >> 3) & 7)) * 16));
    uint32_t bDst0 = (uint32_t)((tid >> 4) * 256 + ((((tid & 15)) ^ ((tid >> 4) & 7)) * 16));
    int l15 = lane & 15;
    int lc  = lane >> 4;
    int sA7 = l15 & 7;
    uint32_t aOff[2];
    #pragma unroll
    for (int mf = 0; mf < 2; mf++)
        aOff[mf] = (uint32_t)((wm*32 + mf*16 + l15) * 128);
    uint32_t bOff[4];
    #pragma unroll
    for (int nf2 = 0; nf2 < 4; nf2++) {
        int nc = wn*8 + nf2*2 + lc;
        bOff[nf2] = (uint32_t)(l15*256 + ((nc ^ sA7) * 16));
    }

    for (int t = blockIdx.x; t < NTILES; t += GPERS) {
        int bx = t % NX, by = t / NX;
        int e = by >> 6, m = by & 63;
        int off = g_expert_off[e];
        int cnt = g_expert_off[e+1] - off;
        if (m * BM >= cnt) continue;
        int mbase = off + m * BM;
        int rv = min(cnt - m * BM, BM);
        int n0 = bx * BN;

        const __half* wbase = W + (size_t)e * K * NTOT + n0;

        const char* aSrc[4];
        #pragma unroll
        for (int i = 0; i < 4; i++) {
            int r = i*32 + (tid >> 3);
            int rr = min(r, rv - 1);
            int arow = IS_FC ? g_perm_tok[mbase + rr] : (mbase + rr);
            aSrc[i] = (const char*)(A + (size_t)arow * K) + (tid & 7) * 16;
        }
        const char* bSrc0 = (const char*)(wbase + (size_t)(tid >> 4) * NTOT) + (tid & 15) * 16;

        float acc[2][NFRAG][4];
        #pragma unroll
        for (int i = 0; i < 2; i++)
            #pragma unroll
            for (int j = 0; j < NFRAG; j++)
                #pragma unroll
                for (int v = 0; v < 4; v++) acc[i][j][v] = 0.0f;

        auto issue = [&](int kt, uint32_t stageOff) {
            uint32_t base = sbase + stageOff;
            #pragma unroll
            for (int i = 0; i < 4; i++)
                CP_ASYNC16(base + aDst0 + i * 4096, aSrc[i] + (size_t)kt * (BK*2));
            #pragma unroll
            for (int i = 0; i < 4; i++)
                CP_ASYNC16(base + A_BYTES + bDst0 + i * 4096,
                           bSrc0 + (size_t)kt * ((size_t)BK * NTOT * 2) + (size_t)i * (16*(size_t)NTOT*2));
        };

        // guard: all warps done reading previous tile's smem
        __syncthreads();

        issue(0, 0); CP_COMMIT();
        issue(1, STAGE_BYTES); CP_COMMIT();

        uint32_t ldOff = 0, stOff = 2*STAGE_BYTES;

        for (int kt = 0; kt < NCH; kt++) {
            CP_WAIT1();
            __syncthreads();
            if (kt + 2 < NCH) issue(kt + 2, stOff);
            CP_COMMIT();

            uint32_t aBase = sbase + ldOff;
            uint32_t bBase = aBase + A_BYTES;

            #pragma unroll
            for (int ks = 0; ks < 4; ks++) {
                uint32_t kShiftA = (uint32_t)((((ks*2 + lc) ^ sA7) * 16));
                uint32_t af[2][4];
                #pragma unroll
                for (int mf = 0; mf < 2; mf++)
                    LDSM_X4(af[mf][0], af[mf][1], af[mf][2], af[mf][3],
                            aBase + aOff[mf] + kShiftA);
                uint32_t bf[NFRAG][2];
                #pragma unroll
                for (int nf2 = 0; nf2 < NFRAG/2; nf2++)
                    LDSM_X4_T(bf[2*nf2][0], bf[2*nf2][1], bf[2*nf2+1][0], bf[2*nf2+1][1],
                              bBase + (uint32_t)(ks*4096) + bOff[nf2]);
                #pragma unroll
                for (int mf = 0; mf < 2; mf++)
                    #pragma unroll
                    for (int nf = 0; nf < NFRAG; nf++)
                        mma_fp16(acc[mf][nf], af[mf], bf[nf]);
            }

            ldOff += STAGE_BYTES; if (ldOff == (uint32_t)SMEM_TOTAL) ldOff = 0;
            stOff += STAGE_BYTES; if (stOff == (uint32_t)SMEM_TOTAL) stOff = 0;
        }

        // ---- epilogue ----
        const float* brow = bias + (size_t)e * NTOT + n0;

        #pragma unroll
        for (int mf = 0; mf < 2; mf++) {
            int r0 = wm*32 + mf*16 + g;
            int r1 = r0 + 8;
            #pragma unroll
            for (int nf = 0; nf < NFRAG; nf++) {
                int col = wn*64 + nf*8 + tig*2;
                float2 bb = *reinterpret_cast<const float2*>(brow + col);
                if (IS_FC) {
                    __half2* o0 = reinterpret_cast<__half2*>(g_hbufh + (size_t)(mbase + r0) * NTOT + n0 + col);
                    __half2* o1 = reinterpret_cast<__half2*>(g_hbufh + (size_t)(mbase + r1) * NTOT + n0 + col);
                    if (r0 < rv)
                        *o0 = __floats2half2_rn(gelu_tanh(acc[mf][nf][0] + bb.x),
                                                gelu_tanh(acc[mf][nf][1] + bb.y));
                    if (r1 < rv)
                        *o1 = __floats2half2_rn(gelu_tanh(acc[mf][nf][2] + bb.x),
                                                gelu_tanh(acc[mf][nf][3] + bb.y));
                } else {
                    float* o0 = g_ybuf + (size_t)(mbase + r0) * NTOT + n0 + col;
                    float* o1 = g_ybuf + (size_t)(mbase + r1) * NTOT + n0 + col;
                    if (r0 < rv) {
                        float2 o; o.x = acc[mf][nf][0] + bb.x; o.y = acc[mf][nf][1] + bb.y;
                        *reinterpret_cast<float2*>(o0) = o;
                    }
                    if (r1 < rv) {
                        float2 o; o.x = acc[mf][nf][2] + bb.x; o.y = acc[mf][nf][3] + bb.y;
                        *reinterpret_cast<float2*>(o1) = o;
                    }
                }
            }
        }
    }
}

// ---------------------------------------------------------------------------
// Combine: out[t] = g0 * y[p0] + g1 * y[p1]
// ---------------------------------------------------------------------------
__global__ void __launch_bounds__(256) combine_kernel(float* __restrict__ out)
{
    int t = blockIdx.x;
    int j = threadIdx.x;
    int p0 = g_inv_pos[2*t], p1 = g_inv_pos[2*t+1];
    float g0 = g_tok_gate[2*t], g1 = g_tok_gate[2*t+1];
    const float4* y0 = reinterpret_cast<const float4*>(g_ybuf + (size_t)p0 * DMODEL);
    const float4* y1 = reinterpret_cast<const float4*>(g_ybuf + (size_t)p1 * DMODEL);
    float4 a = y0[j], b = y1[j];
    float4 o;
    o.x = g0*a.x + g1*b.x; o.y = g0*a.y + g1*b.y;
    o.z = g0*a.z + g1*b.z; o.w = g0*a.w + g1*b.w;
    reinterpret_cast<float4*>(out + (size_t)t * DMODEL)[j] = o;
}

// ---------------------------------------------------------------------------
extern "C" void kernel_launch(void* const* d_in, const int* in_sizes, int n_in,
                              void* d_out, int out_size)
{
    const float* x      = (const float*)d_in[0];
    const float* noise  = (const float*)d_in[1];
    const float* wroute = (const float*)d_in[2];
    const float* broute = (const float*)d_in[3];
    const float* wnoise = (const float*)d_in[4];
    const float* bnoise = (const float*)d_in[5];
    const float* wfc    = (const float*)d_in[6];
    const float* bfc    = (const float*)d_in[7];
    const float* wproj  = (const float*)d_in[8];
    const float* bproj  = (const float*)d_in[9];

    float* out   = (float*)d_out;
    float* gate1 = out + (size_t)TOK * DMODEL;

    cudaFuncSetAttribute((const void*)moe_gemm_fp16<DMODEL, HDIM, 32, true>,
        cudaFuncAttributeMaxDynamicSharedMemorySize, SMEM_TOTAL);
    cudaFuncSetAttribute((const void*)moe_gemm_fp16<HDIM, DMODEL, 8, false>,
        cudaFuncAttributeMaxDynamicSharedMemorySize, SMEM_TOTAL);

    __half *xh_p, *wfch_p, *wprojh_p, *hbufh_p;
    cudaGetSymbolAddress((void**)&xh_p, g_xh);
    cudaGetSymbolAddress((void**)&wfch_p, g_wfch);
    cudaGetSymbolAddress((void**)&wprojh_p, g_wprojh);
    cudaGetSymbolAddress((void**)&hbufh_p, g_hbufh);

    // router + both weight conversions
    router_conv_kernel<<<4736, 256>>>(
        x, noise, wroute, broute, wnoise, bnoise, gate1, xh_p,
        wfc, wfch_p, NEXP*DMODEL*HDIM/4,
        wproj, wprojh_p, NEXP*HDIM*DMODEL/4);

    partition_kernel<<<1, 1024>>>();

    moe_gemm_fp16<DMODEL, HDIM, 32, true><<<GPERS, 256, SMEM_TOTAL>>>(xh_p, wfch_p, bfc);
    moe_gemm_fp16<HDIM, DMODEL, 8, false><<<GPERS, 256, SMEM_TOTAL>>>(hbufh_p, wprojh_p, bproj);

    combine_kernel<<<TOK, 256>>>(out);
}

// round 16
// speedup vs baseline: 1.1964x; 1.1294x over previous
#include <cuda_runtime.h>
#include <cuda_fp16.h>
#include <math.h>
#include <cstdint>

// Problem constants
#define TOK    4096
#define DMODEL 1024
#define NEXP   8
#define HDIM   4096
#define NASSIGN (TOK*2)

#define BM 128
#define BN 128
#define BK 64              // k-halves per stage
#define NSTAGE 3
#define A_BYTES 16384      // 128 rows x 64 halves (128B/row)
#define B_BYTES 16384      // 64 rows x 128 halves (256B/row)
#define STAGE_BYTES (A_BYTES + B_BYTES)     // 32768
#define SMEM_TOTAL (NSTAGE*STAGE_BYTES)     // 98304 -> 2 CTAs/SM
#define MAXTILES 71        // sum_e ceil(cnt_e/128) <= 64 + 7

// Scratch (device globals; allocation-free rule)
__device__ int    g_expert_off[NEXP+1];
__device__ int    g_perm_tok[NASSIGN];
__device__ int    g_inv_pos[NASSIGN];
__device__ int    g_tok_exp[NASSIGN];
__device__ float  g_tok_gate[NASSIGN];
__device__ int    g_n_tiles;
__device__ int4   g_tiles[MAXTILES];        // (e, mbase, rv, unused)
__device__ __half g_xh[(size_t)TOK * DMODEL];
__device__ __half g_wfch[(size_t)NEXP * DMODEL * HDIM];
__device__ __half g_wprojh[(size_t)NEXP * HDIM * DMODEL];
__device__ __half g_hbufh[(size_t)NASSIGN * HDIM];
__device__ float  g_ybuf[(size_t)NASSIGN * DMODEL];

// ---------------------------------------------------------------------------
__device__ __forceinline__ uint32_t smem_u32(const void* p) {
    uint32_t a;
    asm("{ .reg .u64 t; cvta.to.shared.u64 t, %1; cvt.u32.u64 %0, t; }" : "=r"(a) : "l"(p));
    return a;
}
#define CP_ASYNC16(dst, src) \
    asm volatile("cp.async.cg.shared.global [%0], [%1], 16;" :: "r"(dst), "l"(src))
#define CP_COMMIT() asm volatile("cp.async.commit_group;")
#define CP_WAIT1()  asm volatile("cp.async.wait_group 1;")

#define LDSM_X4(R0,R1,R2,R3,ADDR) \
    asm volatile("ldmatrix.sync.aligned.m8n8.x4.shared.b16 {%0,%1,%2,%3}, [%4];" \
        : "=r"(R0),"=r"(R1),"=r"(R2),"=r"(R3) : "r"(ADDR))
#define LDSM_X4_T(R0,R1,R2,R3,ADDR) \
    asm volatile("ldmatrix.sync.aligned.m8n8.x4.trans.shared.b16 {%0,%1,%2,%3}, [%4];" \
        : "=r"(R0),"=r"(R1),"=r"(R2),"=r"(R3) : "r"(ADDR))

__device__ __forceinline__ void mma_fp16(float* c, const uint32_t* a, const uint32_t* b) {
    asm volatile(
        "mma.sync.aligned.m16n8k16.row.col.f32.f16.f16.f32 "
        "{%0,%1,%2,%3}, {%4,%5,%6,%7}, {%8,%9}, {%0,%1,%2,%3};"
        : "+f"(c[0]), "+f"(c[1]), "+f"(c[2]), "+f"(c[3])
        : "r"(a[0]), "r"(a[1]), "r"(a[2]), "r"(a[3]), "r"(b[0]), "r"(b[1]));
}

__device__ __forceinline__ float tanh_fast(float x) {
    float r; asm("tanh.approx.f32 %0, %1;" : "=f"(r) : "f"(x)); return r;
}
__device__ __forceinline__ float gelu_tanh(float v) {
    const float c = 0.7978845608028654f;
    float u = c * (v + 0.044715f * v * v * v);
    return 0.5f * v * (1.0f + tanh_fast(u));
}

// ---------------------------------------------------------------------------
// Merged router + weight conversion (R10 structure, both tensors).
// ---------------------------------------------------------------------------
__global__ void __launch_bounds__(256) router_conv_kernel(
    const float* __restrict__ x, const float* __restrict__ noise,
    const float* __restrict__ wr, const float* __restrict__ br,
    const float* __restrict__ wn, const float* __restrict__ bn,
    float* __restrict__ gate1, __half* __restrict__ xh,
    const float* __restrict__ wfcs, __half* __restrict__ wfcd, int n4a,
    const float* __restrict__ wprojs, __half* __restrict__ wprojd, int n4b)
{
    int lane = threadIdx.x & 31;
    int wid  = threadIdx.x >> 5;
    int tid  = threadIdx.x;

    int rblk = (blockIdx.x % 9 == 0) ? (int)(blockIdx.x / 9) : -1;
    if (rblk >= 0 && rblk < TOK/8) {
        int warp = rblk * 8 + wid;   // token id

        const float4* xr4 = reinterpret_cast<const float4*>(x + (size_t)warp * DMODEL);
        float4 xv4[8];
        #pragma unroll
        for (int j = 0; j < 8; j++) xv4[j] = xr4[j*32 + lane];

        __half2* xh2 = reinterpret_cast<__half2*>(xh + (size_t)warp * DMODEL);
        #pragma unroll
        for (int j = 0; j < 8; j++) {
            xh2[(j*32 + lane)*2 + 0] = __floats2half2_rn(xv4[j].x, xv4[j].y);
            xh2[(j*32 + lane)*2 + 1] = __floats2half2_rn(xv4[j].z, xv4[j].w);
        }

        float ar[8] = {0,0,0,0,0,0,0,0};
        float an[8] = {0,0,0,0,0,0,0,0};
        #pragma unroll
        for (int j = 0; j < 8; j++) {
            #pragma unroll
            for (int c = 0; c < 4; c++) {
                float xv = (c == 0) ? xv4[j].x : (c == 1) ? xv4[j].y : (c == 2) ? xv4[j].z : xv4[j].w;
                int d = j*128 + lane*4 + c;
                const float4* w4r = reinterpret_cast<const float4*>(wr + (size_t)d*8);
                const float4* w4n = reinterpret_cast<const float4*>(wn + (size_t)d*8);
                float4 r0 = w4r[0], r1 = w4r[1];
                float4 n0 = w4n[0], n1 = w4n[1];
                ar[0] = fmaf(xv, r0.x, ar[0]); ar[1] = fmaf(xv, r0.y, ar[1]);
                ar[2] = fmaf(xv, r0.z, ar[2]); ar[3] = fmaf(xv, r0.w, ar[3]);
                ar[4] = fmaf(xv, r1.x, ar[4]); ar[5] = fmaf(xv, r1.y, ar[5]);
                ar[6] = fmaf(xv, r1.z, ar[6]); ar[7] = fmaf(xv, r1.w, ar[7]);
                an[0] = fmaf(xv, n0.x, an[0]); an[1] = fmaf(xv, n0.y, an[1]);
                an[2] = fmaf(xv, n0.z, an[2]); an[3] = fmaf(xv, n0.w, an[3]);
                an[4] = fmaf(xv, n1.x, an[4]); an[5] = fmaf(xv, n1.y, an[5]);
                an[6] = fmaf(xv, n1.z, an[6]); an[7] = fmaf(xv, n1.w, an[7]);
            }
        }
        #pragma unroll
        for (int e = 0; e < 8; e++) {
            #pragma unroll
            for (int o = 16; o > 0; o >>= 1) {
                ar[e] += __shfl_xor_sync(0xffffffffu, ar[e], o);
                an[e] += __shfl_xor_sync(0xffffffffu, an[e], o);
            }
        }
        if (lane == 0) {
            float nv[8];
            float mx = -1e30f;
            #pragma unroll
            for (int e = 0; e < 8; e++) {
                float l  = ar[e] + br[e];
                float nl = an[e] + bn[e];
                float sp = fmaxf(nl, 0.0f) + log1pf(expf(-fabsf(nl)));
                float v = l + noise[(size_t)warp*8 + e] * sp;
                nv[e] = v;
                mx = fmaxf(mx, v);
            }
            float s = 0.0f;
            #pragma unroll
            for (int e = 0; e < 8; e++) s += expf(nv[e] - mx);
            float inv = 1.0f / s;
            #pragma unroll
            for (int e = 0; e < 8; e++) gate1[(size_t)warp*8 + e] = expf(nv[e] - mx) * inv;
            int i0 = 0;
            #pragma unroll
            for (int e = 1; e < 8; e++) if (nv[e] > nv[i0]) i0 = e;
            int i1 = -1;
            #pragma unroll
            for (int e = 0; e < 8; e++) {
                if (e == i0) continue;
                if (i1 < 0 || nv[e] > nv[i1]) i1 = e;
            }
            float ex = expf(nv[i1] - nv[i0]);
            float den = 1.0f + ex;
            g_tok_exp[warp*2 + 0]  = i0;
            g_tok_exp[warp*2 + 1]  = i1;
            g_tok_gate[warp*2 + 0] = 1.0f / den;
            g_tok_gate[warp*2 + 1] = ex / den;
        }
    }

    // grid-stride weight conversion (all blocks, both tensors)
    int i = blockIdx.x * blockDim.x + tid;
    int stride = gridDim.x * blockDim.x;
    int total = n4a + n4b;
    for (; i < total; i += stride) {
        const float* s; __half* d; int j;
        if (i < n4a) { s = wfcs;   d = wfcd;   j = i; }
        else         { s = wprojs; d = wprojd; j = i - n4a; }
        float4 v = reinterpret_cast<const float4*>(s)[j];
        __half2 h0 = __floats2half2_rn(v.x, v.y);
        __half2 h1 = __floats2half2_rn(v.z, v.w);
        reinterpret_cast<__half2*>(d)[2*j]   = h0;
        reinterpret_cast<__half2*>(d)[2*j+1] = h1;
    }
}

// ---------------------------------------------------------------------------
// Deterministic stable partition + compact tile table.
// 1024 threads, 8 assigns each.
// ---------------------------------------------------------------------------
__global__ void __launch_bounds__(1024) partition_kernel()
{
    __shared__ int wtot[32][8];
    __shared__ int wbase[32][8];
    __shared__ int ebase[9];
    int tid = threadIdx.x, lane = tid & 31, w = tid >> 5;
    int a0 = tid * 8;

    int ex[8];
    int local[8] = {0,0,0,0,0,0,0,0};
    #pragma unroll
    for (int i = 0; i < 8; i++) { ex[i] = g_tok_exp[a0 + i]; local[ex[i]]++; }

    int incl[8];
    #pragma unroll
    for (int e = 0; e < 8; e++) incl[e] = local[e];
    #pragma unroll
    for (int off = 1; off < 32; off <<= 1) {
        #pragma unroll
        for (int e = 0; e < 8; e++) {
            int v = __shfl_up_sync(0xffffffffu, incl[e], off);
            if (lane >= off) incl[e] += v;
        }
    }
    if (lane == 31) {
        #pragma unroll
        for (int e = 0; e < 8; e++) wtot[w][e] = incl[e];
    }
    __syncthreads();

    if (w == 0) {
        int t[8], ti[8];
        #pragma unroll
        for (int e = 0; e < 8; e++) { t[e] = wtot[lane][e]; ti[e] = t[e]; }
        #pragma unroll
        for (int off = 1; off < 32; off <<= 1) {
            #pragma unroll
            for (int e = 0; e < 8; e++) {
                int v = __shfl_up_sync(0xffffffffu, ti[e], off);
                if (lane >= off) ti[e] += v;
            }
        }
        #pragma unroll
        for (int e = 0; e < 8; e++) wbase[lane][e] = ti[e] - t[e];
        if (lane == 31) {
            int acc = 0;
            #pragma unroll
            for (int e = 0; e < 8; e++) { ebase[e] = acc; acc += ti[e]; }
            ebase[8] = acc;
            #pragma unroll
            for (int e = 0; e <= 8; e++) g_expert_off[e] = ebase[e];
        }
    }
    __syncthreads();

    // compact tile table (serial, <=71 entries)
    if (tid == 0) {
        int nt = 0;
        for (int e = 0; e < 8; e++) {
            int off = ebase[e];
            int cnt = ebase[e+1] - ebase[e];
            for (int j = 0; j * BM < cnt; j++) {
                int4 tt;
                tt.x = e;
                tt.y = off + j * BM;
                tt.z = min(cnt - j * BM, BM);
                tt.w = 0;
                g_tiles[nt++] = tt;
            }
        }
        g_n_tiles = nt;
    }

    int pos[8];
    #pragma unroll
    for (int e = 0; e < 8; e++) pos[e] = ebase[e] + wbase[w][e] + incl[e] - local[e];
    #pragma unroll
    for (int i = 0; i < 8; i++) {
        int e = ex[i];
        int p = pos[e]++;
        g_perm_tok[p] = (a0 + i) >> 1;
        g_inv_pos[a0 + i] = p;
    }
}

// ---------------------------------------------------------------------------
// fp16 mma.sync GEMM — hot path identical to R10 (125 regs, no slack).
// Tile identity comes from the compact table: grid.y <= MAXTILES.
// ---------------------------------------------------------------------------
template<int K, int NTOT, bool IS_FC>
__global__ void __launch_bounds__(256, 2) moe_gemm_fp16(
    const __half* __restrict__ A,
    const __half* __restrict__ W,
    const float* __restrict__ bias)
{
    constexpr int NCH = K / BK;
    constexpr int NFRAG = 8;

    extern __shared__ char smem[];
    if ((int)blockIdx.y >= g_n_tiles) return;
    int4 tt = g_tiles[blockIdx.y];
    int e = tt.x, mbase = tt.y, rv = tt.z;
    int n0 = blockIdx.x * BN;

    int tid = threadIdx.x;
    int lane = tid & 31, wid = tid >> 5;
    int wm = wid & 3, wn = wid >> 2;        // 4 x 2 warp grid
    int g = lane >> 2, tig = lane & 3;

    uint32_t sbase = smem_u32(smem);
    const __half* wbase = W + (size_t)e * K * NTOT + n0;

    // ---- staging descriptors ----
    const char* aSrc[4];
    #pragma unroll
    for (int i = 0; i < 4; i++) {
        int r = i*32 + (tid >> 3);
        int rr = min(r, rv - 1);
        int arow = IS_FC ? g_perm_tok[mbase + rr] : (mbase + rr);
        aSrc[i] = (const char*)(A + (size_t)arow * K) + (tid & 7) * 16;
    }
    uint32_t aDst0 = (uint32_t)((tid >> 3) * 128 + (((tid & 7) ^ ((tid >> 3) & 7)) * 16));
    const char* bSrc0 = (const char*)(wbase + (size_t)(tid >> 4) * NTOT) + (tid & 15) * 16;
    uint32_t bDst0 = (uint32_t)((tid >> 4) * 256 + ((((tid & 15)) ^ ((tid >> 4) & 7)) * 16));

    float acc[2][NFRAG][4];
    #pragma unroll
    for (int i = 0; i < 2; i++)
        #pragma unroll
        for (int j = 0; j < NFRAG; j++)
            #pragma unroll
            for (int v = 0; v < 4; v++) acc[i][j][v] = 0.0f;

    auto issue = [&](int kt, uint32_t stageOff) {
        uint32_t base = sbase + stageOff;
        #pragma unroll
        for (int i = 0; i < 4; i++)
            CP_ASYNC16(base + aDst0 + i * 4096, aSrc[i] + (size_t)kt * (BK*2));
        #pragma unroll
        for (int i = 0; i < 4; i++)
            CP_ASYNC16(base + A_BYTES + bDst0 + i * 4096,
                       bSrc0 + (size_t)kt * ((size_t)BK * NTOT * 2) + (size_t)i * (16*(size_t)NTOT*2));
    };

    issue(0, 0); CP_COMMIT();
    issue(1, STAGE_BYTES); CP_COMMIT();

    // per-lane ldmatrix offsets (kt/ks-invariant parts precomputed)
    int l15 = lane & 15;
    int lc  = lane >> 4;
    int sA7 = l15 & 7;
    uint32_t aOff[2];
    #pragma unroll
    for (int mf = 0; mf < 2; mf++)
        aOff[mf] = (uint32_t)((wm*32 + mf*16 + l15) * 128);
    uint32_t bOff[4];
    #pragma unroll
    for (int nf2 = 0; nf2 < 4; nf2++) {
        int nc = wn*8 + nf2*2 + lc;
        bOff[nf2] = (uint32_t)(l15*256 + ((nc ^ sA7) * 16));
    }

    uint32_t ldOff = 0, stOff = 2*STAGE_BYTES;

    for (int kt = 0; kt < NCH; kt++) {
        CP_WAIT1();
        __syncthreads();
        if (kt + 2 < NCH) issue(kt + 2, stOff);
        CP_COMMIT();

        uint32_t aBase = sbase + ldOff;
        uint32_t bBase = aBase + A_BYTES;

        #pragma unroll
        for (int ks = 0; ks < 4; ks++) {
            uint32_t kShiftA = (uint32_t)((((ks*2 + lc) ^ sA7) * 16));
            uint32_t af[2][4];
            #pragma unroll
            for (int mf = 0; mf < 2; mf++)
                LDSM_X4(af[mf][0], af[mf][1], af[mf][2], af[mf][3],
                        aBase + aOff[mf] + kShiftA);
            uint32_t bf[NFRAG][2];
            #pragma unroll
            for (int nf2 = 0; nf2 < NFRAG/2; nf2++)
                LDSM_X4_T(bf[2*nf2][0], bf[2*nf2][1], bf[2*nf2+1][0], bf[2*nf2+1][1],
                          bBase + (uint32_t)(ks*4096) + bOff[nf2]);
            #pragma unroll
            for (int mf = 0; mf < 2; mf++)
                #pragma unroll
                for (int nf = 0; nf < NFRAG; nf++)
                    mma_fp16(acc[mf][nf], af[mf], bf[nf]);
        }

        ldOff += STAGE_BYTES; if (ldOff == (uint32_t)SMEM_TOTAL) ldOff = 0;
        stOff += STAGE_BYTES; if (stOff == (uint32_t)SMEM_TOTAL) stOff = 0;
    }

    // ---- epilogue ----
    const float* brow = bias + (size_t)e * NTOT + n0;

    #pragma unroll
    for (int mf = 0; mf < 2; mf++) {
        int r0 = wm*32 + mf*16 + g;
        int r1 = r0 + 8;
        #pragma unroll
        for (int nf = 0; nf < NFRAG; nf++) {
            int col = wn*64 + nf*8 + tig*2;
            float2 bb = *reinterpret_cast<const float2*>(brow + col);
            if (IS_FC) {
                __half2* o0 = reinterpret_cast<__half2*>(g_hbufh + (size_t)(mbase + r0) * NTOT + n0 + col);
                __half2* o1 = reinterpret_cast<__half2*>(g_hbufh + (size_t)(mbase + r1) * NTOT + n0 + col);
                if (r0 < rv)
                    *o0 = __floats2half2_rn(gelu_tanh(acc[mf][nf][0] + bb.x),
                                            gelu_tanh(acc[mf][nf][1] + bb.y));
                if (r1 < rv)
                    *o1 = __floats2half2_rn(gelu_tanh(acc[mf][nf][2] + bb.x),
                                            gelu_tanh(acc[mf][nf][3] + bb.y));
            } else {
                float* o0 = g_ybuf + (size_t)(mbase + r0) * NTOT + n0 + col;
                float* o1 = g_ybuf + (size_t)(mbase + r1) * NTOT + n0 + col;
                if (r0 < rv) {
                    float2 o; o.x = acc[mf][nf][0] + bb.x; o.y = acc[mf][nf][1] + bb.y;
                    *reinterpret_cast<float2*>(o0) = o;
                }
                if (r1 < rv) {
                    float2 o; o.x = acc[mf][nf][2] + bb.x; o.y = acc[mf][nf][3] + bb.y;
                    *reinterpret_cast<float2*>(o1) = o;
                }
            }
        }
    }
}

// ---------------------------------------------------------------------------
// Combine: out[t] = g0 * y[p0] + g1 * y[p1]
// ---------------------------------------------------------------------------
__global__ void __launch_bounds__(256) combine_kernel(float* __restrict__ out)
{
    int t = blockIdx.x;
    int j = threadIdx.x;
    int p0 = g_inv_pos[2*t], p1 = g_inv_pos[2*t+1];
    float g0 = g_tok_gate[2*t], g1 = g_tok_gate[2*t+1];
    const float4* y0 = reinterpret_cast<const float4*>(g_ybuf + (size_t)p0 * DMODEL);
    const float4* y1 = reinterpret_cast<const float4*>(g_ybuf + (size_t)p1 * DMODEL);
    float4 a = y0[j], b = y1[j];
    float4 o;
    o.x = g0*a.x + g1*b.x; o.y = g0*a.y + g1*b.y;
    o.z = g0*a.z + g1*b.z; o.w = g0*a.w + g1*b.w;
    reinterpret_cast<float4*>(out + (size_t)t * DMODEL)[j] = o;
}

// ---------------------------------------------------------------------------
extern "C" void kernel_launch(void* const* d_in, const int* in_sizes, int n_in,
                              void* d_out, int out_size)
{
    const float* x      = (const float*)d_in[0];
    const float* noise  = (const float*)d_in[1];
    const float* wroute = (const float*)d_in[2];
    const float* broute = (const float*)d_in[3];
    const float* wnoise = (const float*)d_in[4];
    const float* bnoise = (const float*)d_in[5];
    const float* wfc    = (const float*)d_in[6];
    const float* bfc    = (const float*)d_in[7];
    const float* wproj  = (const float*)d_in[8];
    const float* bproj  = (const float*)d_in[9];

    float* out   = (float*)d_out;
    float* gate1 = out + (size_t)TOK * DMODEL;

    cudaFuncSetAttribute((const void*)moe_gemm_fp16<DMODEL, HDIM, true>,
        cudaFuncAttributeMaxDynamicSharedMemorySize, SMEM_TOTAL);
    cudaFuncSetAttribute((const void*)moe_gemm_fp16<HDIM, DMODEL, false>,
        cudaFuncAttributeMaxDynamicSharedMemorySize, SMEM_TOTAL);

    __half *xh_p, *wfch_p, *wprojh_p, *hbufh_p;
    cudaGetSymbolAddress((void**)&xh_p, g_xh);
    cudaGetSymbolAddress((void**)&wfch_p, g_wfch);
    cudaGetSymbolAddress((void**)&wprojh_p, g_wprojh);
    cudaGetSymbolAddress((void**)&hbufh_p, g_hbufh);

    // router + both weight conversions
    router_conv_kernel<<<4736, 256>>>(
        x, noise, wroute, broute, wnoise, bnoise, gate1, xh_p,
        wfc, wfch_p, NEXP*DMODEL*HDIM/4,
        wproj, wprojh_p, NEXP*HDIM*DMODEL/4);

    partition_kernel<<<1, 1024>>>();

    dim3 g1(HDIM / BN, MAXTILES);     // 32 x 71
    moe_gemm_fp16<DMODEL, HDIM, true><<<g1, 256, SMEM_TOTAL>>>(xh_p, wfch_p, bfc);

    dim3 g2(DMODEL / BN, MAXTILES);   // 8 x 71
    moe_gemm_fp16<HDIM, DMODEL, false><<<g2, 256, SMEM_TOTAL>>>(hbufh_p, wprojh_p, bproj);

    combine_kernel<<<TOK, 256>>>(out);
}